// round 1
// baseline (speedup 1.0000x reference)
#include <cuda_runtime.h>
#include <cuda_bf16.h>
#include <math_constants.h>

#define BB 4
#define KK 8192
#define THREADS 256
#define RM 4
#define TN 512
#define NSPLIT 8
#define RED_BLOCKS 64

// Scratch (no cudaMalloc allowed): per-point partial minima as order-preserving
// uint bits (distances are nonnegative), plus fixed partial-sum slots.
__device__ unsigned int g_min[2][BB * KK];
__device__ float g_part[3][RED_BLOCKS];

__global__ void init_kernel() {
    int i = blockIdx.x * blockDim.x + threadIdx.x;
    if (i < 2 * BB * KK) ((unsigned int*)g_min)[i] = 0x7F800000u;  // +inf
}

// dir=0: owned=pred, other=target (min_p2t). dir=1: swapped (min_t2p).
// Each thread owns RM points, block covers 1024 owned points x (K/NSPLIT) others.
__global__ void __launch_bounds__(THREADS)
chamfer_min_kernel(const float* __restrict__ pred, const float* __restrict__ target) {
    const int dir = blockIdx.z;
    const float* __restrict__ A = dir ? target : pred;
    const float* __restrict__ Bp = dir ? pred : target;
    unsigned int* __restrict__ outmin = g_min[dir];

    const int b      = blockIdx.y;
    const int tile   = blockIdx.x / NSPLIT;
    const int jsplit = blockIdx.x % NSPLIT;
    const int tid    = threadIdx.x;

    __shared__ float4 sh[TN];

    float nx[RM], ny[RM], nz[RM], p2[RM], m[RM];
    const int ibase = tile * (THREADS * RM) + tid;
#pragma unroll
    for (int r = 0; r < RM; r++) {
        const int i = ibase + r * THREADS;
        const float* p = A + ((size_t)b * KK + i) * 3;
        float x = p[0], y = p[1], z = p[2];
        nx[r] = -x; ny[r] = -y; nz[r] = -z;
        p2[r] = x * x + y * y + z * z;
        m[r] = CUDART_INF_F;
    }

    const int j0 = jsplit * (KK / NSPLIT);
    const int j1 = j0 + (KK / NSPLIT);

    for (int jc = j0; jc < j1; jc += TN) {
        __syncthreads();
#pragma unroll
        for (int u = 0; u < TN / THREADS; u++) {
            const int j = jc + tid + u * THREADS;
            const float* t = Bp + ((size_t)b * KK + j) * 3;
            float x = t[0], y = t[1], z = t[2];
            sh[tid + u * THREADS] = make_float4(x, y, z, 0.5f * (x * x + y * y + z * z));
        }
        __syncthreads();

        // v_j = c_j - dot(p, t_j); min over j.  d2 = p2 + 2*min(v).
#pragma unroll 4
        for (int j = 0; j < TN; j++) {
            const float4 t = sh[j];
#pragma unroll
            for (int r = 0; r < RM; r++) {
                float v = fmaf(nz[r], t.z, t.w);
                v = fmaf(ny[r], t.y, v);
                v = fmaf(nx[r], t.x, v);
                m[r] = fminf(m[r], v);
            }
        }
    }

#pragma unroll
    for (int r = 0; r < RM; r++) {
        float d2 = fmaf(2.0f, m[r], p2[r]);
        float d  = sqrtf(fmaxf(d2, 0.0f));
        atomicMin(&outmin[(size_t)b * KK + ibase + r * THREADS], __float_as_uint(d));
    }
}

__global__ void __launch_bounds__(THREADS)
reduce_kernel(const float* __restrict__ mask) {
    float s0 = 0.f, s1 = 0.f, s2 = 0.f;
    for (int i = blockIdx.x * blockDim.x + threadIdx.x; i < BB * KK;
         i += gridDim.x * blockDim.x) {
        float mk = mask[i];
        s0 = fmaf(__uint_as_float(g_min[0][i]), mk, s0);
        s1 = fmaf(__uint_as_float(g_min[1][i]), mk, s1);
        s2 += mk;
    }
    __shared__ float sh[3][THREADS];
    int tid = threadIdx.x;
    sh[0][tid] = s0; sh[1][tid] = s1; sh[2][tid] = s2;
    __syncthreads();
    for (int off = THREADS / 2; off > 0; off >>= 1) {
        if (tid < off) {
            sh[0][tid] += sh[0][tid + off];
            sh[1][tid] += sh[1][tid + off];
            sh[2][tid] += sh[2][tid + off];
        }
        __syncthreads();
    }
    if (tid == 0) {
        g_part[0][blockIdx.x] = sh[0][0];
        g_part[1][blockIdx.x] = sh[1][0];
        g_part[2][blockIdx.x] = sh[2][0];
    }
}

__global__ void final_kernel(float* __restrict__ out) {
    float s0 = 0.f, s1 = 0.f, s2 = 0.f;
    for (int i = 0; i < RED_BLOCKS; i++) {
        s0 += g_part[0][i];
        s1 += g_part[1][i];
        s2 += g_part[2][i];
    }
    out[0] = (s0 + s1) / (2.0f * (s2 + 1e-8f));
}

extern "C" void kernel_launch(void* const* d_in, const int* in_sizes, int n_in,
                              void* d_out, int out_size) {
    const float* pred   = (const float*)d_in[0];
    const float* target = (const float*)d_in[1];
    const float* mask   = (const float*)d_in[2];
    float* out = (float*)d_out;

    init_kernel<<<(2 * BB * KK + THREADS - 1) / THREADS, THREADS>>>();

    dim3 grid(KK / (THREADS * RM) * NSPLIT, BB, 2);
    chamfer_min_kernel<<<grid, THREADS>>>(pred, target);

    reduce_kernel<<<RED_BLOCKS, THREADS>>>(mask);
    final_kernel<<<1, 1>>>(out);
}

// round 2
// speedup vs baseline: 1.0604x; 1.0604x over previous
#include <cuda_runtime.h>
#include <cuda_bf16.h>
#include <math_constants.h>

#define BB 4
#define KK 8192
#define THREADS 256
#define RM 4
#define TN 512
#define TNP (TN / 2)
#define NSPLIT 8
#define RTHREADS 1024

// Scratch (no cudaMalloc allowed): per-point minima as order-preserving uint
// bits (distances are nonnegative).
__device__ unsigned int g_min[2][BB * KK];

typedef unsigned long long u64;

__device__ __forceinline__ u64 pack2(float lo, float hi) {
    u64 r;
    asm("mov.b64 %0, {%1, %2};" : "=l"(r) : "f"(lo), "f"(hi));
    return r;
}
__device__ __forceinline__ void unpack2(u64 v, float& lo, float& hi) {
    asm("mov.b64 {%0, %1}, %2;" : "=f"(lo), "=f"(hi) : "l"(v));
}
__device__ __forceinline__ u64 ffma2(u64 a, u64 b, u64 c) {
    u64 d;
    asm("fma.rn.f32x2 %0, %1, %2, %3;" : "=l"(d) : "l"(a), "l"(b), "l"(c));
    return d;
}

__global__ void init_kernel() {
    int i = blockIdx.x * blockDim.x + threadIdx.x;
    if (i < 2 * BB * KK) ((unsigned int*)g_min)[i] = 0x7F800000u;  // +inf
}

// dir=0: owned=pred, other=target (min_p2t). dir=1: swapped (min_t2p).
// Shared tile stored PRE-PACKED as f32x2 j-pairs (SoA) so the hot loop has no
// pack MOVs: per j-pair, 4x LDS.64 + 3*RM FFMA2 + 2*RM FMNMX.
__global__ void __launch_bounds__(THREADS)
chamfer_min_kernel(const float* __restrict__ pred, const float* __restrict__ target) {
    const int dir = blockIdx.z;
    const float* __restrict__ A  = dir ? target : pred;
    const float* __restrict__ Bp = dir ? pred : target;
    unsigned int* __restrict__ outmin = g_min[dir];

    const int b      = blockIdx.y;
    const int tile   = blockIdx.x / NSPLIT;
    const int jsplit = blockIdx.x % NSPLIT;
    const int tid    = threadIdx.x;

    __shared__ u64 shx[TNP], shy[TNP], shz[TNP], shw[TNP];

    u64 nx2[RM], ny2[RM], nz2[RM];
    float p2[RM], m[RM];
    const int ibase = tile * (THREADS * RM) + tid;
#pragma unroll
    for (int r = 0; r < RM; r++) {
        const int i = ibase + r * THREADS;
        const float* p = A + ((size_t)b * KK + i) * 3;
        float x = p[0], y = p[1], z = p[2];
        nx2[r] = pack2(-x, -x);
        ny2[r] = pack2(-y, -y);
        nz2[r] = pack2(-z, -z);
        p2[r] = x * x + y * y + z * z;
        m[r] = CUDART_INF_F;
    }

    const int j0 = jsplit * (KK / NSPLIT);
    const int j1 = j0 + (KK / NSPLIT);

    for (int jc = j0; jc < j1; jc += TN) {
        __syncthreads();
        {
            // thread tid packs j-pair (jc+2*tid, jc+2*tid+1)
            const float* t = Bp + ((size_t)b * KK + jc + 2 * tid) * 3;
            float x0 = t[0], y0 = t[1], z0 = t[2];
            float x1 = t[3], y1 = t[4], z1 = t[5];
            shx[tid] = pack2(x0, x1);
            shy[tid] = pack2(y0, y1);
            shz[tid] = pack2(z0, z1);
            shw[tid] = pack2(0.5f * (x0 * x0 + y0 * y0 + z0 * z0),
                             0.5f * (x1 * x1 + y1 * y1 + z1 * z1));
        }
        __syncthreads();

        // v_j = 0.5*|t_j|^2 - dot(p, t_j); min over j.  d2 = p2 + 2*min(v).
#pragma unroll 4
        for (int jp = 0; jp < TNP; jp++) {
            const u64 tx = shx[jp], ty = shy[jp], tz = shz[jp], tw = shw[jp];
#pragma unroll
            for (int r = 0; r < RM; r++) {
                u64 v = ffma2(nz2[r], tz, tw);
                v = ffma2(ny2[r], ty, v);
                v = ffma2(nx2[r], tx, v);
                float vlo, vhi;
                unpack2(v, vlo, vhi);
                m[r] = fminf(m[r], vlo);
                m[r] = fminf(m[r], vhi);
            }
        }
    }

#pragma unroll
    for (int r = 0; r < RM; r++) {
        float d2 = fmaf(2.0f, m[r], p2[r]);
        float d  = sqrtf(fmaxf(d2, 0.0f));
        atomicMin(&outmin[(size_t)b * KK + ibase + r * THREADS], __float_as_uint(d));
    }
}

// Single-block fused reduction: deterministic fixed-order sums.
__global__ void __launch_bounds__(RTHREADS)
reduce_kernel(const float* __restrict__ mask, float* __restrict__ out) {
    float s0 = 0.f, s1 = 0.f, s2 = 0.f;
    for (int i = threadIdx.x; i < BB * KK; i += RTHREADS) {
        float mk = mask[i];
        s0 = fmaf(__uint_as_float(g_min[0][i]), mk, s0);
        s1 = fmaf(__uint_as_float(g_min[1][i]), mk, s1);
        s2 += mk;
    }
    __shared__ float sh[3][RTHREADS];
    const int tid = threadIdx.x;
    sh[0][tid] = s0; sh[1][tid] = s1; sh[2][tid] = s2;
    __syncthreads();
    for (int off = RTHREADS / 2; off > 0; off >>= 1) {
        if (tid < off) {
            sh[0][tid] += sh[0][tid + off];
            sh[1][tid] += sh[1][tid + off];
            sh[2][tid] += sh[2][tid + off];
        }
        __syncthreads();
    }
    if (tid == 0)
        out[0] = (sh[0][0] + sh[1][0]) / (2.0f * (sh[2][0] + 1e-8f));
}

extern "C" void kernel_launch(void* const* d_in, const int* in_sizes, int n_in,
                              void* d_out, int out_size) {
    const float* pred   = (const float*)d_in[0];
    const float* target = (const float*)d_in[1];
    const float* mask   = (const float*)d_in[2];
    float* out = (float*)d_out;

    init_kernel<<<(2 * BB * KK + THREADS - 1) / THREADS, THREADS>>>();

    dim3 grid(KK / (THREADS * RM) * NSPLIT, BB, 2);
    chamfer_min_kernel<<<grid, THREADS>>>(pred, target);

    reduce_kernel<<<1, RTHREADS>>>(mask, out);
}